// round 1
// baseline (speedup 1.0000x reference)
#include <cuda_runtime.h>

#define NB 256
#define XB 256
#define TB 3
#define KB 64
#define AB 193
#define EPSF 1e-9f

// single global accumulator (double for order-insensitive-enough accuracy)
__device__ double g_sum;

__global__ void k_init() { g_sum = 0.0; }

// ---------------------------------------------------------------------------
// Kernel 1: loss0 + loss1 + loss2 over all (n,x,t,k). Coalesced k-major walk.
// ---------------------------------------------------------------------------
__global__ void k_main(const float* __restrict__ pred, const float* __restrict__ gt) {
    const int total = NB * XB * TB * KB;           // 12,582,912  (fits int)
    const int stride = gridDim.x * blockDim.x;
    float acc = 0.f;
    for (int idx = blockIdx.x * blockDim.x + threadIdx.x; idx < total; idx += stride) {
        int k   = idx & 63;
        int row = idx >> 6;
        int pb  = row * AB;
        float px = pred[pb + k];
        float pv = pred[pb + 128 + k];
        float gx = gt[pb + k];
        float gv = gt[pb + 128 + k];
        float gc = gt[pb + 192];
        // loss0 (note EPS on (1-gv) term, matching reference)
        acc += -(gv * logf(pv + EPSF) + (1.f - gv + EPSF) * logf(1.f - pv + EPSF)) * (1.f / (float)KB);
        // loss2
        acc += fabsf(gc * gv * (px - gx));
        // loss1 (once per row)
        if (k == 0) {
            float pc = pred[pb + 192];
            acc += -(gc * logf(pc + EPSF) + (1.f - gc) * logf(1.f - pc + EPSF));
        }
    }
    __shared__ float s[256];
    s[threadIdx.x] = acc;
    __syncthreads();
    for (int o = 128; o > 0; o >>= 1) {
        if (threadIdx.x < o) s[threadIdx.x] += s[threadIdx.x + o];
        __syncthreads();
    }
    if (threadIdx.x == 0) atomicAdd(&g_sum, (double)s[0]);
}

// ---------------------------------------------------------------------------
// Kernel 2: per-batch compaction + lane width / height losses (loss3, loss4).
// One block (256 threads, 8 warps) per batch n.
// ---------------------------------------------------------------------------
__global__ void __launch_bounds__(256) k_lanes(
    const float* __restrict__ pred, const float* __restrict__ gt,
    const float* __restrict__ hcam_arr, const float* __restrict__ ax,
    const float* __restrict__ ay, const float* __restrict__ xstd,
    const float* __restrict__ zstd)
{
    const int n    = blockIdx.x;
    const int tid  = threadIdx.x;
    const int lane = tid & 31;
    const int wid  = tid >> 5;

    __shared__ int   s_sel[XB];
    __shared__ int   s_nsel;
    __shared__ int   s_wcnt[8];
    __shared__ float s_cs[4][KB];
    __shared__ int   s_ck[KB];
    __shared__ int   s_ncols;
    __shared__ float s_lw[8], s_lh[8];

    const float* gtn = gt   + (size_t)n * XB * TB * AB;
    const float* prn = pred + (size_t)n * XB * TB * AB;

    // --- step 1: sel[x] = gt_class[n,x,t=0] > 0; stable compaction ---
    {
        int x = tid;
        float gc0 = gtn[(size_t)x * TB * AB + (AB - 1)];
        bool sel = gc0 > 0.f;
        unsigned b = __ballot_sync(0xffffffffu, sel);
        if (lane == 0) s_wcnt[wid] = __popc(b);
        __syncthreads();
        int wbase = 0;
#pragma unroll
        for (int w = 0; w < 8; w++) wbase += (w < wid) ? s_wcnt[w] : 0;
        int pos = wbase + __popc(b & ((1u << lane) - 1u));
        if (sel) s_sel[pos] = x;
        if (tid == 255) s_nsel = pos + (sel ? 1 : 0);
        __syncthreads();
    }
    const int nsel  = s_nsel;
    const int nrows = nsel * 3;

    // --- step 2: col_sum over selected rows; keep; stable column compaction ---
    {
        int k = tid & 63, part = tid >> 6;
        float cs = 0.f;
        for (int r = part; r < nrows; r += 4) {
            int q = r / 3;
            int x = s_sel[q];
            int t = r - q * 3;
            cs += gtn[((size_t)x * TB + t) * AB + 128 + k];
        }
        s_cs[part][k] = cs;
        __syncthreads();
        if (tid == 0) {
            int nc = 0;
            float nf = (float)nrows;
            for (int kk = 0; kk < KB; kk++) {
                float tot = s_cs[0][kk] + s_cs[1][kk] + s_cs[2][kk] + s_cs[3][kk];
                if (tot >= nf || kk < 5) s_ck[nc++] = kk;
            }
            s_ncols = nc;
        }
        __syncthreads();
    }
    const int   ncols = s_ncols;   // always >= 5
    const float hcam  = hcam_arr[n];
    const float xstd0 = xstd[0];

    float lwacc = 0.f, lhacc = 0.f;
    const int npairs = nrows - 1;  // nrows is 0 or >=3, so loop is safe/empty

    // --- step 3: warp per row-pair, lanes sweep compacted columns ---
    for (int i = wid; i < npairs; i += 8) {
        int qA = i / 3,       tA = i - qA * 3;       int xA = s_sel[qA];
        int rB = i + 1;
        int qB = rB / 3,      tBv = rB - qB * 3;     int xB = s_sel[qB];
        const float* pA = prn + ((size_t)xA * TB + tA)  * AB;
        const float* gA = gtn + ((size_t)xA * TB + tA)  * AB;
        const float* pB = prn + ((size_t)xB * TB + tBv) * AB;
        const float* gB = gtn + ((size_t)xB * TB + tBv) * AB;
        float axA = ax[xA], axB = ax[xB];

        // width0 from unscaled gt_Xg at original k=0
        float w_prev_carry = fabsf((gB[0] * xstd0 + axB) - (gA[0] * xstd0 + axA));
        float carry_lane = 0.f, carry_Y = 0.f;

        for (int jb = 0; jb < ncols; jb += 32) {
            int  jj  = jb + lane;
            bool act = jj < ncols;
            int  c   = s_ck[act ? jj : (ncols - 1)];
            float zsd = zstd[c];
            float ZA = pA[KB + c] * zsd;
            float ZB = pB[KB + c] * zsd;
            float sA = 1.f - ZA / hcam;
            float sB = 1.f - ZB / hcam;
            float laneA = sA * (gA[c] * xstd[c] + axA);
            float laneB = sB * (gB[c] * xstd[c] + axB);
            float YA = sA * ay[c];

            float pl = __shfl_up_sync(0xffffffffu, laneA, 1);
            float py = __shfl_up_sync(0xffffffffu, YA, 1);
            if (lane == 0) { pl = carry_lane; py = carry_Y; }
            float ddy = YA - py;
            float ddl = laneA - pl;
            float dy  = fabsf(ddy);
            float dxy = sqrtf(ddl * ddl + ddy * ddy);
            float lY = dy, l = dxy;
            if (jb == 0) {
                float dy1 = __shfl_sync(0xffffffffu, dy, 1);
                if (lane == 0) { lY = dy1; l = dy1; }   // lY[:,0]=dY[:,0]; l[:,0]=lY[:,0]
            }
            float w  = fabsf(laneB - laneA) * lY / (l + EPSF);
            float pw = __shfl_up_sync(0xffffffffu, w, 1);
            if (lane == 0) pw = w_prev_carry;
            if (act) {
                lwacc += fabsf(w - pw);
                lhacc += fabsf(ZB - ZA);
            }
            carry_lane   = __shfl_sync(0xffffffffu, laneA, 31);
            carry_Y      = __shfl_sync(0xffffffffu, YA, 31);
            w_prev_carry = __shfl_sync(0xffffffffu, w, 31);
        }
    }

    // reduce
#pragma unroll
    for (int o = 16; o > 0; o >>= 1) {
        lwacc += __shfl_xor_sync(0xffffffffu, lwacc, o);
        lhacc += __shfl_xor_sync(0xffffffffu, lhacc, o);
    }
    if (lane == 0) { s_lw[wid] = lwacc; s_lh[wid] = lhacc; }
    __syncthreads();
    if (tid == 0) {
        float lw = 0.f, lh = 0.f;
#pragma unroll
        for (int w = 0; w < 8; w++) { lw += s_lw[w]; lh += s_lh[w]; }
        atomicAdd(&g_sum, 5.0 * ((double)lw + (double)lh));
    }
}

__global__ void k_final(float* out) { out[0] = (float)g_sum; }

extern "C" void kernel_launch(void* const* d_in, const int* in_sizes, int n_in,
                              void* d_out, int out_size) {
    const float* pred = (const float*)d_in[0];
    const float* gt   = (const float*)d_in[1];
    const float* hcam = (const float*)d_in[2];
    const float* axs  = (const float*)d_in[3];
    const float* ays  = (const float*)d_in[4];
    const float* xstd = (const float*)d_in[5];
    const float* zstd = (const float*)d_in[6];

    k_init<<<1, 1>>>();
    k_main<<<1184, 256>>>(pred, gt);
    k_lanes<<<NB, 256>>>(pred, gt, hcam, axs, ays, xstd, zstd);
    k_final<<<1, 1>>>((float*)d_out);
}

// round 2
// speedup vs baseline: 1.9104x; 1.9104x over previous
#include <cuda_runtime.h>

#define NB 256
#define XB 256
#define TB 3
#define KB 64
#define AB 193
#define ROWS (NB * XB * TB)        // 196608
#define EPSF 1e-9f

#define MAIN_BLOCKS 6528
#define UPT 2                      // units per thread; 6528*256*2 = 196608*17 exactly

__device__ float g_part_main[MAIN_BLOCKS];
__device__ float g_part_lanes[NB];

// ---------------------------------------------------------------------------
// Kernel 1: loss0 + loss1 + loss2. One "unit" = (row, j) with j in [0,17).
// Four aligned float4 loads per unit (pred/gt x xoff/vis) share alignment
// phase a = row & 3, covering k = 4j - a + {0..3}. k==64 is the class scalar.
// ---------------------------------------------------------------------------
__global__ void __launch_bounds__(256) k_main(const float* __restrict__ pred,
                                              const float* __restrict__ gt) {
    const int gid = blockIdx.x * 256 + threadIdx.x;
    const int gstride = MAIN_BLOCKS * 256;
    float acc = 0.f;

#pragma unroll
    for (int t = 0; t < UPT; t++) {
        int u   = gid + t * gstride;
        int row = u / 17;
        int j   = u - row * 17;
        int a   = row & 3;
        int rb  = row * AB;
        int bx  = rb - a + 4 * j;      // 16B-aligned xoff window
        int bv  = bx + 128;            // 16B-aligned vis window (same phase)

        float4 px4 = *reinterpret_cast<const float4*>(pred + bx);
        float4 gx4 = *reinterpret_cast<const float4*>(gt   + bx);
        float4 pv4 = *reinterpret_cast<const float4*>(pred + bv);
        float4 gv4 = *reinterpret_cast<const float4*>(gt   + bv);
        float  gc  = __ldg(gt + rb + 192);

        int k0 = 4 * j - a;
        float pxs[4] = {px4.x, px4.y, px4.z, px4.w};
        float gxs[4] = {gx4.x, gx4.y, gx4.z, gx4.w};
        float pvs[4] = {pv4.x, pv4.y, pv4.z, pv4.w};
        float gvs[4] = {gv4.x, gv4.y, gv4.z, gv4.w};

#pragma unroll
        for (int i = 0; i < 4; i++) {
            int k = k0 + i;
            float pv = pvs[i], gv = gvs[i];
            if (k >= 0 && k < 64) {
                // loss0 (note EPS on the (1-gv) term)
                acc += -(gv * __logf(pv + EPSF) +
                         (1.f - gv + EPSF) * __logf(1.f - pv + EPSF)) * (1.f / 64.f);
                // loss2
                acc += fabsf(gc * gv * (pxs[i] - gxs[i]));
            } else if (k == 64) {
                // here (pv, gv) are (pred_class, gt_class); loss1: no EPS on (1-gc)
                acc += -(gv * __logf(pv + EPSF) +
                         (1.f - gv) * __logf(1.f - pv + EPSF));
            }
        }
    }

    __shared__ float s[256];
    s[threadIdx.x] = acc;
    __syncthreads();
    for (int o = 128; o > 0; o >>= 1) {
        if (threadIdx.x < o) s[threadIdx.x] += s[threadIdx.x + o];
        __syncthreads();
    }
    if (threadIdx.x == 0) g_part_main[blockIdx.x] = s[0];
}

// ---------------------------------------------------------------------------
// Kernel 2: per-batch compaction + lane width / height losses (loss3, loss4).
// One block (256 threads, 8 warps) per batch n. Fast path: ncols<=8 ->
// 4 row-pairs per warp in 8-lane shfl segments.
// ---------------------------------------------------------------------------
__global__ void __launch_bounds__(256) k_lanes(
    const float* __restrict__ pred, const float* __restrict__ gt,
    const float* __restrict__ hcam_arr, const float* __restrict__ ax,
    const float* __restrict__ ay, const float* __restrict__ xstd,
    const float* __restrict__ zstd)
{
    const int n    = blockIdx.x;
    const int tid  = threadIdx.x;
    const int lane = tid & 31;
    const int wid  = tid >> 5;
    const unsigned FULL = 0xffffffffu;

    __shared__ int   s_sel[XB];
    __shared__ int   s_nsel;
    __shared__ int   s_wcnt[8];
    __shared__ float s_cs[4][KB];
    __shared__ int   s_ck[KB];
    __shared__ int   s_ncols;
    __shared__ float s_lw[8], s_lh[8];

    const float* gtn = gt   + (size_t)n * XB * TB * AB;
    const float* prn = pred + (size_t)n * XB * TB * AB;

    // --- step 1: sel[x] = gt_class[n,x,t=0] > 0; stable compaction ---
    {
        int x = tid;
        float gc0 = gtn[(size_t)x * TB * AB + (AB - 1)];
        bool sel = gc0 > 0.f;
        unsigned b = __ballot_sync(FULL, sel);
        if (lane == 0) s_wcnt[wid] = __popc(b);
        __syncthreads();
        int wbase = 0;
#pragma unroll
        for (int w = 0; w < 8; w++) wbase += (w < wid) ? s_wcnt[w] : 0;
        int pos = wbase + __popc(b & ((1u << lane) - 1u));
        if (sel) s_sel[pos] = x;
        if (tid == 255) s_nsel = pos + (sel ? 1 : 0);
        __syncthreads();
    }
    const int nsel  = s_nsel;
    const int nrows = nsel * 3;

    // --- step 2: col_sum over selected rows; keep; stable column compaction ---
    {
        int k = tid & 63, part = tid >> 6;
        float cs = 0.f;
        for (int r = part; r < nrows; r += 4) {
            int q = r / 3;
            int x = s_sel[q];
            int t = r - q * 3;
            cs += gtn[((size_t)x * TB + t) * AB + 128 + k];
        }
        s_cs[part][k] = cs;
        __syncthreads();
        if (tid == 0) {
            int nc = 0;
            float nf = (float)nrows;
            for (int kk = 0; kk < KB; kk++) {
                float tot = s_cs[0][kk] + s_cs[1][kk] + s_cs[2][kk] + s_cs[3][kk];
                if (tot >= nf || kk < 5) s_ck[nc++] = kk;
            }
            s_ncols = nc;
        }
        __syncthreads();
    }
    const int   ncols = s_ncols;   // always >= 5
    const float hcam  = hcam_arr[n];
    const float xstd0 = xstd[0];

    float lwacc = 0.f, lhacc = 0.f;
    const int npairs = nrows - 1;  // nrows is 0 or >=3

    if (ncols <= 8) {
        // ---- fast path: 4 pairs per warp, 8-lane shfl segments ----
        const int sl  = lane & 7;
        const int seg = lane >> 3;
        for (int i0 = wid * 4; i0 < npairs; i0 += 32) {
            int  i      = i0 + seg;
            bool pvalid = i < npairs;
            int  ii     = pvalid ? i : 0;

            int qA = ii / 3,      tA  = ii - qA * 3;      int xA = s_sel[qA];
            int rB = ii + 1;
            int qB = rB / 3,      tBv = rB - qB * 3;      int xB = s_sel[qB];
            const float* pA = prn + ((size_t)xA * TB + tA)  * AB;
            const float* gA = gtn + ((size_t)xA * TB + tA)  * AB;
            const float* pB = prn + ((size_t)xB * TB + tBv) * AB;
            const float* gB = gtn + ((size_t)xB * TB + tBv) * AB;
            float axA = ax[xA], axB = ax[xB];

            float width0 = fabsf((gB[0] * xstd0 + axB) - (gA[0] * xstd0 + axA));

            bool act = pvalid && (sl < ncols);
            int  c   = s_ck[sl < ncols ? sl : (ncols - 1)];
            float zsd = zstd[c];
            float ZA = pA[KB + c] * zsd;
            float ZB = pB[KB + c] * zsd;
            float sA = 1.f - ZA / hcam;
            float sB = 1.f - ZB / hcam;
            float laneA = sA * (gA[c] * xstd[c] + axA);
            float laneB = sB * (gB[c] * xstd[c] + axB);
            float YA = sA * ay[c];

            float pl = __shfl_up_sync(FULL, laneA, 1, 8);
            float py = __shfl_up_sync(FULL, YA, 1, 8);
            float ddy = YA - py;
            float ddl = laneA - pl;
            float dy  = fabsf(ddy);
            float dxy = sqrtf(ddl * ddl + ddy * ddy);
            float lY = dy, l = dxy;
            float dy1 = __shfl_sync(FULL, dy, 1, 8);
            if (sl == 0) { lY = dy1; l = dy1; }   // lY[:,0]=dY[:,0]; l[:,0]=lY[:,0]
            float w  = fabsf(laneB - laneA) * lY / (l + EPSF);
            float pw = __shfl_up_sync(FULL, w, 1, 8);
            if (sl == 0) pw = width0;
            if (act) {
                lwacc += fabsf(w - pw);
                lhacc += fabsf(ZB - ZA);
            }
        }
    } else {
        // ---- generic path: warp per pair, 32-wide sweep with carries ----
        for (int i = wid; i < npairs; i += 8) {
            int qA = i / 3,       tA = i - qA * 3;       int xA = s_sel[qA];
            int rB = i + 1;
            int qB = rB / 3,      tBv = rB - qB * 3;     int xB = s_sel[qB];
            const float* pA = prn + ((size_t)xA * TB + tA)  * AB;
            const float* gA = gtn + ((size_t)xA * TB + tA)  * AB;
            const float* pB = prn + ((size_t)xB * TB + tBv) * AB;
            const float* gB = gtn + ((size_t)xB * TB + tBv) * AB;
            float axA = ax[xA], axB = ax[xB];

            float w_prev_carry = fabsf((gB[0] * xstd0 + axB) - (gA[0] * xstd0 + axA));
            float carry_lane = 0.f, carry_Y = 0.f;

            for (int jb = 0; jb < ncols; jb += 32) {
                int  jj  = jb + lane;
                bool act = jj < ncols;
                int  c   = s_ck[act ? jj : (ncols - 1)];
                float zsd = zstd[c];
                float ZA = pA[KB + c] * zsd;
                float ZB = pB[KB + c] * zsd;
                float sA = 1.f - ZA / hcam;
                float sB = 1.f - ZB / hcam;
                float laneA = sA * (gA[c] * xstd[c] + axA);
                float laneB = sB * (gB[c] * xstd[c] + axB);
                float YA = sA * ay[c];

                float pl = __shfl_up_sync(FULL, laneA, 1);
                float py = __shfl_up_sync(FULL, YA, 1);
                if (lane == 0) { pl = carry_lane; py = carry_Y; }
                float ddy = YA - py;
                float ddl = laneA - pl;
                float dy  = fabsf(ddy);
                float dxy = sqrtf(ddl * ddl + ddy * ddy);
                float lY = dy, l = dxy;
                if (jb == 0) {
                    float dy1 = __shfl_sync(FULL, dy, 1);
                    if (lane == 0) { lY = dy1; l = dy1; }
                }
                float w  = fabsf(laneB - laneA) * lY / (l + EPSF);
                float pw = __shfl_up_sync(FULL, w, 1);
                if (lane == 0) pw = w_prev_carry;
                if (act) {
                    lwacc += fabsf(w - pw);
                    lhacc += fabsf(ZB - ZA);
                }
                carry_lane   = __shfl_sync(FULL, laneA, 31);
                carry_Y      = __shfl_sync(FULL, YA, 31);
                w_prev_carry = __shfl_sync(FULL, w, 31);
            }
        }
    }

    // reduce
#pragma unroll
    for (int o = 16; o > 0; o >>= 1) {
        lwacc += __shfl_xor_sync(FULL, lwacc, o);
        lhacc += __shfl_xor_sync(FULL, lhacc, o);
    }
    if (lane == 0) { s_lw[wid] = lwacc; s_lh[wid] = lhacc; }
    __syncthreads();
    if (tid == 0) {
        float lw = 0.f, lh = 0.f;
#pragma unroll
        for (int w = 0; w < 8; w++) { lw += s_lw[w]; lh += s_lh[w]; }
        g_part_lanes[n] = 5.f * (lw + lh);
    }
}

// ---------------------------------------------------------------------------
// Kernel 3: final reduction of all partials (double accumulation).
// ---------------------------------------------------------------------------
__global__ void __launch_bounds__(256) k_final(float* __restrict__ out) {
    __shared__ double sd[256];
    double s = 0.0;
    for (int i = threadIdx.x; i < MAIN_BLOCKS; i += 256) s += (double)g_part_main[i];
    s += (double)g_part_lanes[threadIdx.x];
    sd[threadIdx.x] = s;
    __syncthreads();
    for (int o = 128; o > 0; o >>= 1) {
        if (threadIdx.x < o) sd[threadIdx.x] += sd[threadIdx.x + o];
        __syncthreads();
    }
    if (threadIdx.x == 0) out[0] = (float)sd[0];
}

extern "C" void kernel_launch(void* const* d_in, const int* in_sizes, int n_in,
                              void* d_out, int out_size) {
    const float* pred = (const float*)d_in[0];
    const float* gt   = (const float*)d_in[1];
    const float* hcam = (const float*)d_in[2];
    const float* axs  = (const float*)d_in[3];
    const float* ays  = (const float*)d_in[4];
    const float* xstd = (const float*)d_in[5];
    const float* zstd = (const float*)d_in[6];

    k_main<<<MAIN_BLOCKS, 256>>>(pred, gt);
    k_lanes<<<NB, 256>>>(pred, gt, hcam, axs, ays, xstd, zstd);
    k_final<<<1, 256>>>((float*)d_out);
}

// round 3
// speedup vs baseline: 2.2889x; 1.1981x over previous
#include <cuda_runtime.h>

#define NB 256
#define XB 256
#define TB 3
#define KB 64
#define AB 193
#define EPSF 1e-9f

#define MAIN_BLOCKS 6528
#define UPT 2                      // 6528*256*2 = 196608*17 exactly
#define TOTAL_BLOCKS (MAIN_BLOCKS + NB)

__device__ float    g_part[TOTAL_BLOCKS];
__device__ unsigned g_count = 0;

// ---------------------------------------------------------------------------
// Fused kernel.
//  blockIdx < NB          : per-batch lane-geometry losses (loss3, loss4)
//  blockIdx >= NB         : elementwise losses (loss0, loss1, loss2)
//  last block to finish   : reduces all partials (double, fixed order) -> out
// ---------------------------------------------------------------------------
__global__ void __launch_bounds__(256) k_fused(
    const float* __restrict__ pred, const float* __restrict__ gt,
    const float* __restrict__ hcam_arr, const float* __restrict__ ax,
    const float* __restrict__ ay, const float* __restrict__ xstd,
    const float* __restrict__ zstd, float* __restrict__ out)
{
    const int tid  = threadIdx.x;
    const int lane = tid & 31;
    const int wid  = tid >> 5;
    const unsigned FULL = 0xffffffffu;

    __shared__ float s_red[256];

    float partial = 0.f;

    if (blockIdx.x >= NB) {
        // =============== MAIN PATH: loss0 + loss1 + loss2 ===============
        const int gid = (blockIdx.x - NB) * 256 + tid;
        const int gstride = MAIN_BLOCKS * 256;
        float acc = 0.f;

#pragma unroll
        for (int t = 0; t < UPT; t++) {
            int u   = gid + t * gstride;
            int row = u / 17;
            int j   = u - row * 17;
            int a   = row & 3;
            int rb  = row * AB;
            int bx  = rb - a + 4 * j;      // 16B-aligned xoff window
            int bv  = bx + 128;            // 16B-aligned vis window (same phase)

            float4 pv4 = *reinterpret_cast<const float4*>(pred + bv);
            float4 gv4 = *reinterpret_cast<const float4*>(gt   + bv);
            float  gc  = __ldg(gt + rb + 192);

            int k0 = 4 * j - a;
            float pvs[4] = {pv4.x, pv4.y, pv4.z, pv4.w};
            float gvs[4] = {gv4.x, gv4.y, gv4.z, gv4.w};

#pragma unroll
            for (int i = 0; i < 4; i++) {
                int k = k0 + i;
                float pv = pvs[i], gv = gvs[i];
                if (k >= 0 && k < 64) {
                    acc += -(gv * __logf(pv + EPSF) +
                             (1.f - gv + EPSF) * __logf(1.f - pv + EPSF)) * (1.f / 64.f);
                } else if (k == 64) {
                    acc += -(gv * __logf(pv + EPSF) +
                             (1.f - gv) * __logf(1.f - pv + EPSF));
                }
            }

            // loss2: exactly zero when gc == 0 (gc in {0,1}) -> skip xoff loads
            if (gc > 0.f) {
                float4 px4 = *reinterpret_cast<const float4*>(pred + bx);
                float4 gx4 = *reinterpret_cast<const float4*>(gt   + bx);
                float pxs[4] = {px4.x, px4.y, px4.z, px4.w};
                float gxs[4] = {gx4.x, gx4.y, gx4.z, gx4.w};
#pragma unroll
                for (int i = 0; i < 4; i++) {
                    int k = k0 + i;
                    if (k >= 0 && k < 64)
                        acc += gvs[i] * fabsf(pxs[i] - gxs[i]);   // gc==1
                }
            }
        }

        // block reduce
        s_red[tid] = acc;
        __syncthreads();
        for (int o = 128; o > 0; o >>= 1) {
            if (tid < o) s_red[tid] += s_red[tid + o];
            __syncthreads();
        }
        partial = s_red[0];
    } else {
        // =============== LANES PATH: loss3 + loss4 (x5) ===============
        const int n = blockIdx.x;
        __shared__ int   s_sel[XB];
        __shared__ int   s_nsel;
        __shared__ int   s_wcnt[8];
        __shared__ int   s_rowoff[768];
        __shared__ float s_ax[768];
        __shared__ float s_cs[4][KB];
        __shared__ int   s_ck[KB];
        __shared__ int   s_ncols;
        __shared__ float s_lw[8], s_lh[8];

        const float* gtn = gt   + (size_t)n * XB * TB * AB;
        const float* prn = pred + (size_t)n * XB * TB * AB;

        // step 1: stable compaction of sel = gt_class[:,t=0] > 0
        {
            int x = tid;
            float gc0 = gtn[(size_t)x * TB * AB + (AB - 1)];
            bool sel = gc0 > 0.f;
            unsigned b = __ballot_sync(FULL, sel);
            if (lane == 0) s_wcnt[wid] = __popc(b);
            __syncthreads();
            int wbase = 0;
#pragma unroll
            for (int w = 0; w < 8; w++) wbase += (w < wid) ? s_wcnt[w] : 0;
            int pos = wbase + __popc(b & ((1u << lane) - 1u));
            if (sel) s_sel[pos] = x;
            if (tid == 255) s_nsel = pos + (sel ? 1 : 0);
            __syncthreads();
        }
        const int nsel  = s_nsel;
        const int nrows = nsel * 3;

        // row offset / anchor tables (kills divides in hot loops)
        for (int r = tid; r < nrows; r += 256) {
            int q = r / 3, t = r - q * 3;
            int x = s_sel[q];
            s_rowoff[r] = (x * TB + t) * AB;
            s_ax[r]     = ax[x];
        }
        __syncthreads();

        // step 2: col_sum over selected rows; keep; stable column compaction
        {
            int k = tid & 63, part = tid >> 6;
            float cs = 0.f;
            for (int r = part; r < nrows; r += 4)
                cs += gtn[s_rowoff[r] + 128 + k];
            s_cs[part][k] = cs;
            __syncthreads();
            if (tid == 0) {
                int nc = 0;
                float nf = (float)nrows;
                for (int kk = 0; kk < KB; kk++) {
                    float tot = s_cs[0][kk] + s_cs[1][kk] + s_cs[2][kk] + s_cs[3][kk];
                    if (tot >= nf || kk < 5) s_ck[nc++] = kk;
                }
                s_ncols = nc;
            }
            __syncthreads();
        }
        const int   ncols = s_ncols;   // always >= 5
        const float hcam  = hcam_arr[n];
        const float xstd0 = xstd[0];

        float lwacc = 0.f, lhacc = 0.f;
        const int npairs = nrows - 1;  // nrows is 0 or >=3

        if (ncols <= 8) {
            // fast path: 4 pairs per warp, 8-lane shfl segments
            const int sl  = lane & 7;
            const int seg = lane >> 3;
            for (int i0 = wid * 4; i0 < npairs; i0 += 32) {
                int  i      = i0 + seg;
                bool pvalid = i < npairs;
                int  ii     = pvalid ? i : 0;
                int offA = s_rowoff[ii],     offB = s_rowoff[ii + 1];
                float axA = s_ax[ii],        axB  = s_ax[ii + 1];
                const float* pA = prn + offA;
                const float* gA = gtn + offA;
                const float* pB = prn + offB;
                const float* gB = gtn + offB;

                float width0 = fabsf((gB[0] * xstd0 + axB) - (gA[0] * xstd0 + axA));

                bool act = pvalid && (sl < ncols);
                int  c   = s_ck[sl < ncols ? sl : (ncols - 1)];
                float zsd = zstd[c];
                float ZA = pA[KB + c] * zsd;
                float ZB = pB[KB + c] * zsd;
                float sA = 1.f - ZA / hcam;
                float sB = 1.f - ZB / hcam;
                float laneA = sA * (gA[c] * xstd[c] + axA);
                float laneB = sB * (gB[c] * xstd[c] + axB);
                float YA = sA * ay[c];

                float pl = __shfl_up_sync(FULL, laneA, 1, 8);
                float py = __shfl_up_sync(FULL, YA, 1, 8);
                float ddy = YA - py;
                float ddl = laneA - pl;
                float dy  = fabsf(ddy);
                float dxy = sqrtf(ddl * ddl + ddy * ddy);
                float lY = dy, l = dxy;
                float dy1 = __shfl_sync(FULL, dy, 1, 8);
                if (sl == 0) { lY = dy1; l = dy1; }
                float w  = fabsf(laneB - laneA) * lY / (l + EPSF);
                float pw = __shfl_up_sync(FULL, w, 1, 8);
                if (sl == 0) pw = width0;
                if (act) {
                    lwacc += fabsf(w - pw);
                    lhacc += fabsf(ZB - ZA);
                }
            }
        } else {
            // generic path: warp per pair, 32-wide sweep with carries
            for (int i = wid; i < npairs; i += 8) {
                int offA = s_rowoff[i],  offB = s_rowoff[i + 1];
                float axA = s_ax[i],     axB  = s_ax[i + 1];
                const float* pA = prn + offA;
                const float* gA = gtn + offA;
                const float* pB = prn + offB;
                const float* gB = gtn + offB;

                float w_prev_carry = fabsf((gB[0] * xstd0 + axB) - (gA[0] * xstd0 + axA));
                float carry_lane = 0.f, carry_Y = 0.f;

                for (int jb = 0; jb < ncols; jb += 32) {
                    int  jj  = jb + lane;
                    bool act = jj < ncols;
                    int  c   = s_ck[act ? jj : (ncols - 1)];
                    float zsd = zstd[c];
                    float ZA = pA[KB + c] * zsd;
                    float ZB = pB[KB + c] * zsd;
                    float sA = 1.f - ZA / hcam;
                    float sB = 1.f - ZB / hcam;
                    float laneA = sA * (gA[c] * xstd[c] + axA);
                    float laneB = sB * (gB[c] * xstd[c] + axB);
                    float YA = sA * ay[c];

                    float pl = __shfl_up_sync(FULL, laneA, 1);
                    float py = __shfl_up_sync(FULL, YA, 1);
                    if (lane == 0) { pl = carry_lane; py = carry_Y; }
                    float ddy = YA - py;
                    float ddl = laneA - pl;
                    float dy  = fabsf(ddy);
                    float dxy = sqrtf(ddl * ddl + ddy * ddy);
                    float lY = dy, l = dxy;
                    if (jb == 0) {
                        float dy1 = __shfl_sync(FULL, dy, 1);
                        if (lane == 0) { lY = dy1; l = dy1; }
                    }
                    float w  = fabsf(laneB - laneA) * lY / (l + EPSF);
                    float pw = __shfl_up_sync(FULL, w, 1);
                    if (lane == 0) pw = w_prev_carry;
                    if (act) {
                        lwacc += fabsf(w - pw);
                        lhacc += fabsf(ZB - ZA);
                    }
                    carry_lane   = __shfl_sync(FULL, laneA, 31);
                    carry_Y      = __shfl_sync(FULL, YA, 31);
                    w_prev_carry = __shfl_sync(FULL, w, 31);
                }
            }
        }

#pragma unroll
        for (int o = 16; o > 0; o >>= 1) {
            lwacc += __shfl_xor_sync(FULL, lwacc, o);
            lhacc += __shfl_xor_sync(FULL, lhacc, o);
        }
        if (lane == 0) { s_lw[wid] = lwacc; s_lh[wid] = lhacc; }
        __syncthreads();
        if (tid == 0) {
            float lw = 0.f, lh = 0.f;
#pragma unroll
            for (int w = 0; w < 8; w++) { lw += s_lw[w]; lh += s_lh[w]; }
            partial = 5.f * (lw + lh);
        }
    }

    // ---------------- publish partial + last-block final reduction ----------
    __shared__ bool s_last;
    if (tid == 0) {
        g_part[blockIdx.x] = partial;
        __threadfence();
        unsigned old = atomicAdd(&g_count, 1u);
        s_last = (old == TOTAL_BLOCKS - 1);
    }
    __syncthreads();

    if (s_last) {
        __threadfence();
        __shared__ double sd[256];
        double s = 0.0;
        for (int i = tid; i < TOTAL_BLOCKS; i += 256) s += (double)g_part[i];
        sd[tid] = s;
        __syncthreads();
        for (int o = 128; o > 0; o >>= 1) {
            if (tid < o) sd[tid] += sd[tid + o];
            __syncthreads();
        }
        if (tid == 0) {
            out[0] = (float)sd[0];
            g_count = 0;             // reset for next graph replay
        }
    }
}

extern "C" void kernel_launch(void* const* d_in, const int* in_sizes, int n_in,
                              void* d_out, int out_size) {
    const float* pred = (const float*)d_in[0];
    const float* gt   = (const float*)d_in[1];
    const float* hcam = (const float*)d_in[2];
    const float* axs  = (const float*)d_in[3];
    const float* ays  = (const float*)d_in[4];
    const float* xstd = (const float*)d_in[5];
    const float* zstd = (const float*)d_in[6];

    k_fused<<<TOTAL_BLOCKS, 256>>>(pred, gt, hcam, axs, ays, xstd, zstd,
                                   (float*)d_out);
}

// round 4
// speedup vs baseline: 2.8254x; 1.2344x over previous
#include <cuda_runtime.h>

#define NB 256
#define XB 256
#define TB 3
#define KB 64
#define AB 193
#define EPSF 1e-9f

#define MAIN_BLOCKS 6528
#define UPT 2                      // 6528*256*2 = 196608*17 exactly
#define TOTAL_BLOCKS (MAIN_BLOCKS + NB)

__device__ float    g_part[TOTAL_BLOCKS];
__device__ unsigned g_count = 0;

// ---------------------------------------------------------------------------
// Fused kernel, capped at 32 regs (launch_bounds 256x8) for full occupancy on
// the DRAM-bound main path. Lanes path may spill; it's 256/6784 blocks and
// hides under the main path's memory stream.
//  blockIdx < NB          : per-batch lane-geometry losses (loss3, loss4)
//  blockIdx >= NB         : elementwise losses (loss0, loss1, loss2)
//  last block to finish   : reduces all partials (double, fixed order) -> out
// ---------------------------------------------------------------------------
__global__ void __launch_bounds__(256, 8) k_fused(
    const float* __restrict__ pred, const float* __restrict__ gt,
    const float* __restrict__ hcam_arr, const float* __restrict__ ax,
    const float* __restrict__ ay, const float* __restrict__ xstd,
    const float* __restrict__ zstd, float* __restrict__ out)
{
    const int tid  = threadIdx.x;
    const int lane = tid & 31;
    const int wid  = tid >> 5;
    const unsigned FULL = 0xffffffffu;

    __shared__ float s_w8[8];

    float partial = 0.f;

    if (blockIdx.x >= NB) {
        // =============== MAIN PATH: loss0 + loss1 + loss2 ===============
        const int gid = (blockIdx.x - NB) * 256 + tid;
        const int gstride = MAIN_BLOCKS * 256;
        float acc = 0.f;

#pragma unroll
        for (int t = 0; t < UPT; t++) {
            int u   = gid + t * gstride;
            int row = u / 17;
            int j   = u - row * 17;
            int a   = row & 3;
            int rb  = row * AB;
            int bx  = rb - a + 4 * j;      // 16B-aligned xoff window
            int bv  = bx + 128;            // 16B-aligned vis window (same phase)

            float4 pv4 = *reinterpret_cast<const float4*>(pred + bv);
            float4 gv4 = *reinterpret_cast<const float4*>(gt   + bv);
            float  gc  = __ldg(gt + rb + 192);

            int k0 = 4 * j - a;
            float pvs[4] = {pv4.x, pv4.y, pv4.z, pv4.w};
            float gvs[4] = {gv4.x, gv4.y, gv4.z, gv4.w};

#pragma unroll
            for (int i = 0; i < 4; i++) {
                int k = k0 + i;
                float pv = pvs[i], gv = gvs[i];
                if (k >= 0 && k < 64) {
                    acc += -(gv * __logf(pv + EPSF) +
                             (1.f - gv + EPSF) * __logf(1.f - pv + EPSF)) * (1.f / 64.f);
                } else if (k == 64) {
                    acc += -(gv * __logf(pv + EPSF) +
                             (1.f - gv) * __logf(1.f - pv + EPSF));
                }
            }

            // loss2: exactly zero when gc == 0 (gc in {0,1}) -> skip xoff loads
            if (gc > 0.f) {
                float4 px4 = *reinterpret_cast<const float4*>(pred + bx);
                float4 gx4 = *reinterpret_cast<const float4*>(gt   + bx);
                float pxs[4] = {px4.x, px4.y, px4.z, px4.w};
                float gxs[4] = {gx4.x, gx4.y, gx4.z, gx4.w};
#pragma unroll
                for (int i = 0; i < 4; i++) {
                    int k = k0 + i;
                    if (k >= 0 && k < 64)
                        acc += gvs[i] * fabsf(pxs[i] - gxs[i]);   // gc==1
                }
            }
        }

        // warp reduce + cross-warp via smem
#pragma unroll
        for (int o = 16; o > 0; o >>= 1)
            acc += __shfl_xor_sync(FULL, acc, o);
        if (lane == 0) s_w8[wid] = acc;
        __syncthreads();
        if (tid == 0) {
            float s = 0.f;
#pragma unroll
            for (int w = 0; w < 8; w++) s += s_w8[w];
            partial = s;
        }
    } else {
        // =============== LANES PATH: loss3 + loss4 (x5) ===============
        const int n = blockIdx.x;
        __shared__ int   s_sel[XB];
        __shared__ int   s_nsel;
        __shared__ int   s_wcnt[8];
        __shared__ int   s_rowoff[768];
        __shared__ float s_ax[768];
        __shared__ float s_cs[4][KB];
        __shared__ int   s_ck[KB];
        __shared__ int   s_ncols;
        __shared__ float s_lw[8], s_lh[8];

        const float* gtn = gt   + (size_t)n * XB * TB * AB;
        const float* prn = pred + (size_t)n * XB * TB * AB;

        // step 1: stable compaction of sel = gt_class[:,t=0] > 0
        {
            int x = tid;
            float gc0 = gtn[(size_t)x * TB * AB + (AB - 1)];
            bool sel = gc0 > 0.f;
            unsigned b = __ballot_sync(FULL, sel);
            if (lane == 0) s_wcnt[wid] = __popc(b);
            __syncthreads();
            int wbase = 0;
#pragma unroll
            for (int w = 0; w < 8; w++) wbase += (w < wid) ? s_wcnt[w] : 0;
            int pos = wbase + __popc(b & ((1u << lane) - 1u));
            if (sel) s_sel[pos] = x;
            if (tid == 255) s_nsel = pos + (sel ? 1 : 0);
            __syncthreads();
        }
        const int nsel  = s_nsel;
        const int nrows = nsel * 3;

        // row offset / anchor tables (kills divides in hot loops)
        for (int r = tid; r < nrows; r += 256) {
            int q = r / 3, t = r - q * 3;
            int x = s_sel[q];
            s_rowoff[r] = (x * TB + t) * AB;
            s_ax[r]     = ax[x];
        }
        __syncthreads();

        // step 2: col_sum over selected rows; keep; stable column compaction
        {
            int k = tid & 63, part = tid >> 6;
            float cs = 0.f;
            for (int r = part; r < nrows; r += 4)
                cs += gtn[s_rowoff[r] + 128 + k];
            s_cs[part][k] = cs;
            __syncthreads();
            if (tid == 0) {
                int nc = 0;
                float nf = (float)nrows;
                for (int kk = 0; kk < KB; kk++) {
                    float tot = s_cs[0][kk] + s_cs[1][kk] + s_cs[2][kk] + s_cs[3][kk];
                    if (tot >= nf || kk < 5) s_ck[nc++] = kk;
                }
                s_ncols = nc;
            }
            __syncthreads();
        }
        const int   ncols = s_ncols;   // always >= 5
        const float hcam  = hcam_arr[n];
        const float xstd0 = xstd[0];

        float lwacc = 0.f, lhacc = 0.f;
        const int npairs = nrows - 1;  // nrows is 0 or >=3

        if (ncols <= 8) {
            // fast path: 4 pairs per warp, 8-lane shfl segments
            const int sl  = lane & 7;
            const int seg = lane >> 3;
            for (int i0 = wid * 4; i0 < npairs; i0 += 32) {
                int  i      = i0 + seg;
                bool pvalid = i < npairs;
                int  ii     = pvalid ? i : 0;
                int offA = s_rowoff[ii],     offB = s_rowoff[ii + 1];
                float axA = s_ax[ii],        axB  = s_ax[ii + 1];
                const float* pA = prn + offA;
                const float* gA = gtn + offA;
                const float* pB = prn + offB;
                const float* gB = gtn + offB;

                float width0 = fabsf((gB[0] * xstd0 + axB) - (gA[0] * xstd0 + axA));

                bool act = pvalid && (sl < ncols);
                int  c   = s_ck[sl < ncols ? sl : (ncols - 1)];
                float zsd = zstd[c];
                float ZA = pA[KB + c] * zsd;
                float ZB = pB[KB + c] * zsd;
                float sA = 1.f - ZA / hcam;
                float sB = 1.f - ZB / hcam;
                float laneA = sA * (gA[c] * xstd[c] + axA);
                float laneB = sB * (gB[c] * xstd[c] + axB);
                float YA = sA * ay[c];

                float pl = __shfl_up_sync(FULL, laneA, 1, 8);
                float py = __shfl_up_sync(FULL, YA, 1, 8);
                float ddy = YA - py;
                float ddl = laneA - pl;
                float dy  = fabsf(ddy);
                float dxy = sqrtf(ddl * ddl + ddy * ddy);
                float lY = dy, l = dxy;
                float dy1 = __shfl_sync(FULL, dy, 1, 8);
                if (sl == 0) { lY = dy1; l = dy1; }
                float w  = fabsf(laneB - laneA) * lY / (l + EPSF);
                float pw = __shfl_up_sync(FULL, w, 1, 8);
                if (sl == 0) pw = width0;
                if (act) {
                    lwacc += fabsf(w - pw);
                    lhacc += fabsf(ZB - ZA);
                }
            }
        } else {
            // generic path: warp per pair, 32-wide sweep with carries
            for (int i = wid; i < npairs; i += 8) {
                int offA = s_rowoff[i],  offB = s_rowoff[i + 1];
                float axA = s_ax[i],     axB  = s_ax[i + 1];
                const float* pA = prn + offA;
                const float* gA = gtn + offA;
                const float* pB = prn + offB;
                const float* gB = gtn + offB;

                float w_prev_carry = fabsf((gB[0] * xstd0 + axB) - (gA[0] * xstd0 + axA));
                float carry_lane = 0.f, carry_Y = 0.f;

                for (int jb = 0; jb < ncols; jb += 32) {
                    int  jj  = jb + lane;
                    bool act = jj < ncols;
                    int  c   = s_ck[act ? jj : (ncols - 1)];
                    float zsd = zstd[c];
                    float ZA = pA[KB + c] * zsd;
                    float ZB = pB[KB + c] * zsd;
                    float sA = 1.f - ZA / hcam;
                    float sB = 1.f - ZB / hcam;
                    float laneA = sA * (gA[c] * xstd[c] + axA);
                    float laneB = sB * (gB[c] * xstd[c] + axB);
                    float YA = sA * ay[c];

                    float pl = __shfl_up_sync(FULL, laneA, 1);
                    float py = __shfl_up_sync(FULL, YA, 1);
                    if (lane == 0) { pl = carry_lane; py = carry_Y; }
                    float ddy = YA - py;
                    float ddl = laneA - pl;
                    float dy  = fabsf(ddy);
                    float dxy = sqrtf(ddl * ddl + ddy * ddy);
                    float lY = dy, l = dxy;
                    if (jb == 0) {
                        float dy1 = __shfl_sync(FULL, dy, 1);
                        if (lane == 0) { lY = dy1; l = dy1; }
                    }
                    float w  = fabsf(laneB - laneA) * lY / (l + EPSF);
                    float pw = __shfl_up_sync(FULL, w, 1);
                    if (lane == 0) pw = w_prev_carry;
                    if (act) {
                        lwacc += fabsf(w - pw);
                        lhacc += fabsf(ZB - ZA);
                    }
                    carry_lane   = __shfl_sync(FULL, laneA, 31);
                    carry_Y      = __shfl_sync(FULL, YA, 31);
                    w_prev_carry = __shfl_sync(FULL, w, 31);
                }
            }
        }

#pragma unroll
        for (int o = 16; o > 0; o >>= 1) {
            lwacc += __shfl_xor_sync(FULL, lwacc, o);
            lhacc += __shfl_xor_sync(FULL, lhacc, o);
        }
        if (lane == 0) { s_lw[wid] = lwacc; s_lh[wid] = lhacc; }
        __syncthreads();
        if (tid == 0) {
            float lw = 0.f, lh = 0.f;
#pragma unroll
            for (int w = 0; w < 8; w++) { lw += s_lw[w]; lh += s_lh[w]; }
            partial = 5.f * (lw + lh);
        }
    }

    // ---------------- publish partial + last-block final reduction ----------
    __shared__ bool s_last;
    if (tid == 0) {
        g_part[blockIdx.x] = partial;
        __threadfence();
        unsigned old = atomicAdd(&g_count, 1u);
        s_last = (old == TOTAL_BLOCKS - 1);
    }
    __syncthreads();

    if (s_last) {
        __threadfence();
        __shared__ double sd[256];
        double s = 0.0;
        for (int i = tid; i < TOTAL_BLOCKS; i += 256) s += (double)g_part[i];
        sd[tid] = s;
        __syncthreads();
        for (int o = 128; o > 0; o >>= 1) {
            if (tid < o) sd[tid] += sd[tid + o];
            __syncthreads();
        }
        if (tid == 0) {
            out[0] = (float)sd[0];
            g_count = 0;             // reset for next graph replay
        }
    }
}

extern "C" void kernel_launch(void* const* d_in, const int* in_sizes, int n_in,
                              void* d_out, int out_size) {
    const float* pred = (const float*)d_in[0];
    const float* gt   = (const float*)d_in[1];
    const float* hcam = (const float*)d_in[2];
    const float* axs  = (const float*)d_in[3];
    const float* ays  = (const float*)d_in[4];
    const float* xstd = (const float*)d_in[5];
    const float* zstd = (const float*)d_in[6];

    k_fused<<<TOTAL_BLOCKS, 256>>>(pred, gt, hcam, axs, ays, xstd, zstd,
                                   (float*)d_out);
}

// round 5
// speedup vs baseline: 2.8273x; 1.0007x over previous
#include <cuda_runtime.h>

#define NB 256
#define XB 256
#define TB 3
#define KB 64
#define AB 193
#define EPSF 1e-9f

#define MAIN_BLOCKS 6528
#define ROWHALF 98304              // rows handled per "unit pass"; 98304*17 = 6528*256
#define TOTAL_BLOCKS (MAIN_BLOCKS + NB)

__device__ float    g_part[TOTAL_BLOCKS];
__device__ unsigned g_count = 0;

// ---------------------------------------------------------------------------
// Fused kernel (32 regs, 8 blocks/SM). gt_vis / gt_class are exactly {0,1},
// so each BCE term needs ONE log: arg = g ? p+e : 1-p+e  (coef 1 vs 1+e).
// Dropping the eps*log(1-p) residue when g==1 costs ~1e-8 relative error.
//  blockIdx <  NB : per-batch lane-geometry losses (loss3, loss4)
//  blockIdx >= NB : elementwise losses (loss0, loss1, loss2), 2 units/thread
//                   with unit2 = row + 98304 (same j, same alignment phase)
// ---------------------------------------------------------------------------
__global__ void __launch_bounds__(256, 8) k_fused(
    const float* __restrict__ pred, const float* __restrict__ gt,
    const float* __restrict__ hcam_arr, const float* __restrict__ ax,
    const float* __restrict__ ay, const float* __restrict__ xstd,
    const float* __restrict__ zstd, float* __restrict__ out)
{
    const int tid  = threadIdx.x;
    const int lane = tid & 31;
    const int wid  = tid >> 5;
    const unsigned FULL = 0xffffffffu;

    __shared__ float s_w8[8];

    float partial = 0.f;

    if (blockIdx.x >= NB) {
        // =============== MAIN PATH: loss0 + loss1 + loss2 ===============
        const int gid = (blockIdx.x - NB) * 256 + tid;
        int row = gid / 17;
        int j   = gid - row * 17;
        int a   = row & 3;                 // (row+98304)&3 == row&3
        int k0  = 4 * j - a;

        const int rb1 = row * AB;
        const int rb2 = rb1 + ROWHALF * AB;
        const int bx1 = rb1 - a + 4 * j;   // 16B-aligned xoff window
        const int bx2 = bx1 + ROWHALF * AB;

        // front-batched independent loads (max MLP)
        float  gc1 = __ldg(gt + rb1 + 192);
        float  gc2 = __ldg(gt + rb2 + 192);
        float4 pvA = *reinterpret_cast<const float4*>(pred + bx1 + 128);
        float4 gvA = *reinterpret_cast<const float4*>(gt   + bx1 + 128);
        float4 pvB = *reinterpret_cast<const float4*>(pred + bx2 + 128);
        float4 gvB = *reinterpret_cast<const float4*>(gt   + bx2 + 128);

        float acc = 0.f;

        {   // ---- unit 1: single-log BCE over vis window ----
            float pvs[4] = {pvA.x, pvA.y, pvA.z, pvA.w};
            float gvs[4] = {gvA.x, gvA.y, gvA.z, gvA.w};
#pragma unroll
            for (int i = 0; i < 4; i++) {
                int k = k0 + i;
                float pv = pvs[i];
                bool g1 = gvs[i] > 0.5f;
                float arg = g1 ? (pv + EPSF) : (1.f - pv + EPSF);
                if ((unsigned)k < 64u) {
                    float cf = g1 ? (1.f / 64.f) : ((1.f + EPSF) / 64.f);
                    acc -= cf * __logf(arg);
                } else if (k == 64) {          // class scalar (loss1, exact)
                    acc -= __logf(arg);
                }
            }
            if (gc1 > 0.f) {                   // loss2 (gc==1 exactly)
                float4 px = *reinterpret_cast<const float4*>(pred + bx1);
                float4 gx = *reinterpret_cast<const float4*>(gt   + bx1);
                float pxs[4] = {px.x, px.y, px.z, px.w};
                float gxs[4] = {gx.x, gx.y, gx.z, gx.w};
#pragma unroll
                for (int i = 0; i < 4; i++)
                    if ((unsigned)(k0 + i) < 64u)
                        acc += gvs[i] * fabsf(pxs[i] - gxs[i]);
            }
        }

        {   // ---- unit 2 ----
            float pvs[4] = {pvB.x, pvB.y, pvB.z, pvB.w};
            float gvs[4] = {gvB.x, gvB.y, gvB.z, gvB.w};
#pragma unroll
            for (int i = 0; i < 4; i++) {
                int k = k0 + i;
                float pv = pvs[i];
                bool g1 = gvs[i] > 0.5f;
                float arg = g1 ? (pv + EPSF) : (1.f - pv + EPSF);
                if ((unsigned)k < 64u) {
                    float cf = g1 ? (1.f / 64.f) : ((1.f + EPSF) / 64.f);
                    acc -= cf * __logf(arg);
                } else if (k == 64) {
                    acc -= __logf(arg);
                }
            }
            if (gc2 > 0.f) {
                float4 px = *reinterpret_cast<const float4*>(pred + bx2);
                float4 gx = *reinterpret_cast<const float4*>(gt   + bx2);
                float pxs[4] = {px.x, px.y, px.z, px.w};
                float gxs[4] = {gx.x, gx.y, gx.z, gx.w};
#pragma unroll
                for (int i = 0; i < 4; i++)
                    if ((unsigned)(k0 + i) < 64u)
                        acc += gvs[i] * fabsf(pxs[i] - gxs[i]);
            }
        }

        // warp reduce + cross-warp via smem
#pragma unroll
        for (int o = 16; o > 0; o >>= 1)
            acc += __shfl_xor_sync(FULL, acc, o);
        if (lane == 0) s_w8[wid] = acc;
        __syncthreads();
        if (tid == 0) {
            float s = 0.f;
#pragma unroll
            for (int w = 0; w < 8; w++) s += s_w8[w];
            partial = s;
        }
    } else {
        // =============== LANES PATH: loss3 + loss4 (x5) ===============
        const int n = blockIdx.x;
        __shared__ int   s_sel[XB];
        __shared__ int   s_nsel;
        __shared__ int   s_wcnt[8];
        __shared__ int   s_rowoff[768];
        __shared__ float s_ax[768];
        __shared__ float s_cs[4][KB];
        __shared__ int   s_ck[KB];
        __shared__ int   s_ncols;
        __shared__ float s_lw[8], s_lh[8];

        const float* gtn = gt   + (size_t)n * XB * TB * AB;
        const float* prn = pred + (size_t)n * XB * TB * AB;

        // step 1: stable compaction of sel = gt_class[:,t=0] > 0
        {
            int x = tid;
            float gc0 = gtn[(size_t)x * TB * AB + (AB - 1)];
            bool sel = gc0 > 0.f;
            unsigned b = __ballot_sync(FULL, sel);
            if (lane == 0) s_wcnt[wid] = __popc(b);
            __syncthreads();
            int wbase = 0;
#pragma unroll
            for (int w = 0; w < 8; w++) wbase += (w < wid) ? s_wcnt[w] : 0;
            int pos = wbase + __popc(b & ((1u << lane) - 1u));
            if (sel) s_sel[pos] = x;
            if (tid == 255) s_nsel = pos + (sel ? 1 : 0);
            __syncthreads();
        }
        const int nsel  = s_nsel;
        const int nrows = nsel * 3;

        for (int r = tid; r < nrows; r += 256) {
            int q = r / 3, t = r - q * 3;
            int x = s_sel[q];
            s_rowoff[r] = (x * TB + t) * AB;
            s_ax[r]     = ax[x];
        }
        __syncthreads();

        // step 2: col_sum over selected rows; keep; stable column compaction
        {
            int k = tid & 63, part = tid >> 6;
            float cs = 0.f;
            for (int r = part; r < nrows; r += 4)
                cs += gtn[s_rowoff[r] + 128 + k];
            s_cs[part][k] = cs;
            __syncthreads();
            if (tid == 0) {
                int nc = 0;
                float nf = (float)nrows;
                for (int kk = 0; kk < KB; kk++) {
                    float tot = s_cs[0][kk] + s_cs[1][kk] + s_cs[2][kk] + s_cs[3][kk];
                    if (tot >= nf || kk < 5) s_ck[nc++] = kk;
                }
                s_ncols = nc;
            }
            __syncthreads();
        }
        const int   ncols = s_ncols;   // always >= 5
        const float hcam  = hcam_arr[n];
        const float xstd0 = xstd[0];

        float lwacc = 0.f, lhacc = 0.f;
        const int npairs = nrows - 1;

        if (ncols <= 8) {
            const int sl  = lane & 7;
            const int seg = lane >> 3;
            for (int i0 = wid * 4; i0 < npairs; i0 += 32) {
                int  i      = i0 + seg;
                bool pvalid = i < npairs;
                int  ii     = pvalid ? i : 0;
                int offA = s_rowoff[ii],     offB = s_rowoff[ii + 1];
                float axA = s_ax[ii],        axB  = s_ax[ii + 1];
                const float* pA = prn + offA;
                const float* gA = gtn + offA;
                const float* pB = prn + offB;
                const float* gB = gtn + offB;

                float width0 = fabsf((gB[0] * xstd0 + axB) - (gA[0] * xstd0 + axA));

                bool act = pvalid && (sl < ncols);
                int  c   = s_ck[sl < ncols ? sl : (ncols - 1)];
                float zsd = zstd[c];
                float ZA = pA[KB + c] * zsd;
                float ZB = pB[KB + c] * zsd;
                float sA = 1.f - ZA / hcam;
                float sB = 1.f - ZB / hcam;
                float laneA = sA * (gA[c] * xstd[c] + axA);
                float laneB = sB * (gB[c] * xstd[c] + axB);
                float YA = sA * ay[c];

                float pl = __shfl_up_sync(FULL, laneA, 1, 8);
                float py = __shfl_up_sync(FULL, YA, 1, 8);
                float ddy = YA - py;
                float ddl = laneA - pl;
                float dy  = fabsf(ddy);
                float dxy = sqrtf(ddl * ddl + ddy * ddy);
                float lY = dy, l = dxy;
                float dy1 = __shfl_sync(FULL, dy, 1, 8);
                if (sl == 0) { lY = dy1; l = dy1; }
                float w  = fabsf(laneB - laneA) * lY / (l + EPSF);
                float pw = __shfl_up_sync(FULL, w, 1, 8);
                if (sl == 0) pw = width0;
                if (act) {
                    lwacc += fabsf(w - pw);
                    lhacc += fabsf(ZB - ZA);
                }
            }
        } else {
            for (int i = wid; i < npairs; i += 8) {
                int offA = s_rowoff[i],  offB = s_rowoff[i + 1];
                float axA = s_ax[i],     axB  = s_ax[i + 1];
                const float* pA = prn + offA;
                const float* gA = gtn + offA;
                const float* pB = prn + offB;
                const float* gB = gtn + offB;

                float w_prev_carry = fabsf((gB[0] * xstd0 + axB) - (gA[0] * xstd0 + axA));
                float carry_lane = 0.f, carry_Y = 0.f;

                for (int jb = 0; jb < ncols; jb += 32) {
                    int  jj  = jb + lane;
                    bool act = jj < ncols;
                    int  c   = s_ck[act ? jj : (ncols - 1)];
                    float zsd = zstd[c];
                    float ZA = pA[KB + c] * zsd;
                    float ZB = pB[KB + c] * zsd;
                    float sA = 1.f - ZA / hcam;
                    float sB = 1.f - ZB / hcam;
                    float laneA = sA * (gA[c] * xstd[c] + axA);
                    float laneB = sB * (gB[c] * xstd[c] + axB);
                    float YA = sA * ay[c];

                    float pl = __shfl_up_sync(FULL, laneA, 1);
                    float py = __shfl_up_sync(FULL, YA, 1);
                    if (lane == 0) { pl = carry_lane; py = carry_Y; }
                    float ddy = YA - py;
                    float ddl = laneA - pl;
                    float dy  = fabsf(ddy);
                    float dxy = sqrtf(ddl * ddl + ddy * ddy);
                    float lY = dy, l = dxy;
                    if (jb == 0) {
                        float dy1 = __shfl_sync(FULL, dy, 1);
                        if (lane == 0) { lY = dy1; l = dy1; }
                    }
                    float w  = fabsf(laneB - laneA) * lY / (l + EPSF);
                    float pw = __shfl_up_sync(FULL, w, 1);
                    if (lane == 0) pw = w_prev_carry;
                    if (act) {
                        lwacc += fabsf(w - pw);
                        lhacc += fabsf(ZB - ZA);
                    }
                    carry_lane   = __shfl_sync(FULL, laneA, 31);
                    carry_Y      = __shfl_sync(FULL, YA, 31);
                    w_prev_carry = __shfl_sync(FULL, w, 31);
                }
            }
        }

#pragma unroll
        for (int o = 16; o > 0; o >>= 1) {
            lwacc += __shfl_xor_sync(FULL, lwacc, o);
            lhacc += __shfl_xor_sync(FULL, lhacc, o);
        }
        if (lane == 0) { s_lw[wid] = lwacc; s_lh[wid] = lhacc; }
        __syncthreads();
        if (tid == 0) {
            float lw = 0.f, lh = 0.f;
#pragma unroll
            for (int w = 0; w < 8; w++) { lw += s_lw[w]; lh += s_lh[w]; }
            partial = 5.f * (lw + lh);
        }
    }

    // ---------------- publish partial + last-block final reduction ----------
    __shared__ bool s_last;
    if (tid == 0) {
        g_part[blockIdx.x] = partial;
        __threadfence();
        unsigned old = atomicAdd(&g_count, 1u);
        s_last = (old == TOTAL_BLOCKS - 1);
    }
    __syncthreads();

    if (s_last) {
        __threadfence();
        __shared__ double sd[256];
        double s = 0.0;
        for (int i = tid; i < TOTAL_BLOCKS; i += 256) s += (double)g_part[i];
        sd[tid] = s;
        __syncthreads();
        for (int o = 128; o > 0; o >>= 1) {
            if (tid < o) sd[tid] += sd[tid + o];
            __syncthreads();
        }
        if (tid == 0) {
            out[0] = (float)sd[0];
            g_count = 0;             // reset for next graph replay
        }
    }
}

extern "C" void kernel_launch(void* const* d_in, const int* in_sizes, int n_in,
                              void* d_out, int out_size) {
    const float* pred = (const float*)d_in[0];
    const float* gt   = (const float*)d_in[1];
    const float* hcam = (const float*)d_in[2];
    const float* axs  = (const float*)d_in[3];
    const float* ays  = (const float*)d_in[4];
    const float* xstd = (const float*)d_in[5];
    const float* zstd = (const float*)d_in[6];

    k_fused<<<TOTAL_BLOCKS, 256>>>(pred, gt, hcam, axs, ays, xstd, zstd,
                                   (float*)d_out);
}